// round 1
// baseline (speedup 1.0000x reference)
#include <cuda_runtime.h>
#include <math.h>

#define C_DIM 270
#define T_DIM 2000
#define O_DIM 270
#define D_DIM 2048
#define NF2   1024   // n_freqs^2 (n_freqs = 32)

#define BM 96
#define BN 128
#define BK 32
#define SA_STRIDE 104   // 96 + 8  (stride % 32 == 8 -> conflict-free frag loads)
#define SB_STRIDE 136   // 128 + 8

// Scratch (device globals: no allocation allowed in kernel_launch)
__device__ float g_emb[C_DIM * D_DIM];     // [c][d]
__device__ float g_scores[O_DIM * C_DIM];  // [o][c]
__device__ float g_wT[C_DIM * O_DIM];      // weights transposed: [c][o]

__device__ __forceinline__ unsigned f2tf(float x) {
    unsigned u;
    asm("cvt.rna.tf32.f32 %0, %1;" : "=r"(u) : "f"(x));
    return u;
}

__device__ __forceinline__ void mma_tf32(float* d, const unsigned* a, const unsigned* b) {
    asm volatile(
        "mma.sync.aligned.m16n8k8.row.col.f32.tf32.tf32.f32 "
        "{%0,%1,%2,%3}, {%4,%5,%6,%7}, {%8,%9}, {%0,%1,%2,%3};\n"
        : "+f"(d[0]), "+f"(d[1]), "+f"(d[2]), "+f"(d[3])
        : "r"(a[0]), "r"(a[1]), "r"(a[2]), "r"(a[3]), "r"(b[0]), "r"(b[1]));
}

// ---------------- Kernel 1: Fourier embedding (batch-invariant) ----------------
__global__ void emb_kernel(const float* __restrict__ layout) {
    int c = blockIdx.x;
    float px = layout[2 * c]     + 0.2f;  // MARGIN
    float py = layout[2 * c + 1] + 0.2f;
    const float w = 6.28318530717958647692f / 1.4f;  // 2*pi / (1 + 2*MARGIN)
    for (int idx = threadIdx.x; idx < NF2; idx += blockDim.x) {
        int i = idx >> 5, j = idx & 31;
        float loc = px * (w * (float)i) + py * (w * (float)j);
        float s, co;
        sincosf(loc, &s, &co);
        g_emb[c * D_DIM + idx]       = co;
        g_emb[c * D_DIM + NF2 + idx] = s;
    }
}

// ---------------- Kernel 2: scores[o,c] = sum_d emb[c,d] * heads[o,d] (fp32) ----
__global__ void __launch_bounds__(256) scores_kernel(const float* __restrict__ heads) {
    __shared__ float sH[32][33];
    __shared__ float sE[32][33];
    int tx = threadIdx.x & 31;   // c within tile
    int ty = threadIdx.x >> 5;   // 0..7
    int ctile = blockIdx.x * 32;
    int otile = blockIdx.y * 32;
    float acc[4] = {0.f, 0.f, 0.f, 0.f};

    int lrow = threadIdx.x >> 3;        // 0..31
    int lk4  = (threadIdx.x & 7) * 4;   // 0,4,...,28

    for (int k0 = 0; k0 < D_DIM; k0 += 32) {
        int orow = otile + lrow;
        float4 h4 = make_float4(0.f, 0.f, 0.f, 0.f);
        if (orow < O_DIM) h4 = *(const float4*)&heads[orow * D_DIM + k0 + lk4];
        sH[lrow][lk4 + 0] = h4.x; sH[lrow][lk4 + 1] = h4.y;
        sH[lrow][lk4 + 2] = h4.z; sH[lrow][lk4 + 3] = h4.w;

        int crow = ctile + lrow;
        float4 e4 = make_float4(0.f, 0.f, 0.f, 0.f);
        if (crow < C_DIM) e4 = *(const float4*)&g_emb[crow * D_DIM + k0 + lk4];
        sE[lrow][lk4 + 0] = e4.x; sE[lrow][lk4 + 1] = e4.y;
        sE[lrow][lk4 + 2] = e4.z; sE[lrow][lk4 + 3] = e4.w;
        __syncthreads();

        #pragma unroll
        for (int k = 0; k < 32; k++) {
            float e = sE[tx][k];
            acc[0] += sH[ty][k]      * e;
            acc[1] += sH[ty + 8][k]  * e;
            acc[2] += sH[ty + 16][k] * e;
            acc[3] += sH[ty + 24][k] * e;
        }
        __syncthreads();
    }

    int c = ctile + tx;
    if (c < C_DIM) {
        #pragma unroll
        for (int r = 0; r < 4; r++) {
            int o = otile + ty + 8 * r;
            if (o < O_DIM) g_scores[o * C_DIM + c] = acc[r];
        }
    }
}

// ---------------- Kernel 3: softmax over c, store transposed W[c][o] ----------
__global__ void softmax_kernel() {
    int o = blockIdx.x;
    int tid = threadIdx.x;
    __shared__ float red[256];

    float m = -1e30f;
    for (int c = tid; c < C_DIM; c += 256) m = fmaxf(m, g_scores[o * C_DIM + c]);
    red[tid] = m; __syncthreads();
    for (int s = 128; s > 0; s >>= 1) {
        if (tid < s) red[tid] = fmaxf(red[tid], red[tid + s]);
        __syncthreads();
    }
    m = red[0]; __syncthreads();

    float sum = 0.f;
    for (int c = tid; c < C_DIM; c += 256) sum += expf(g_scores[o * C_DIM + c] - m);
    red[tid] = sum; __syncthreads();
    for (int s = 128; s > 0; s >>= 1) {
        if (tid < s) red[tid] += red[tid + s];
        __syncthreads();
    }
    float inv = 1.0f / red[0];

    for (int c = tid; c < C_DIM; c += 256)
        g_wT[c * O_DIM + o] = expf(g_scores[o * C_DIM + c] - m) * inv;
}

// ---------------- Kernel 4: out[b] = W @ x[b]  (tf32 mma, 18.7 GFLOP) ---------
__global__ void __launch_bounds__(256) merge_gemm(const float* __restrict__ x,
                                                  float* __restrict__ out) {
    __shared__ float sA[BK][SA_STRIDE];  // W tile, [k][m]
    __shared__ float sB[BK][SB_STRIDE];  // x tile, [k][n]

    int tid = threadIdx.x;
    int b = blockIdx.z;
    int mtile = blockIdx.y * BM;
    int ntile = blockIdx.x * BN;
    int lane = tid & 31, warp = tid >> 5;
    int wm = warp & 1;       // 0..1 -> 48-row half
    int wn = warp >> 1;      // 0..3 -> 32-col quarter
    int g = lane >> 2, tig = lane & 3;

    // B-tile loader indices (float4 along n)
    int bn4 = (lane) * 4;          // use lane for n within the warp's strip
    int bn = (tid & 31) * 4;
    int bk = tid >> 5;             // 0..7
    (void)bn4;

    float acc[3][4][4];
    #pragma unroll
    for (int mt = 0; mt < 3; mt++)
        #pragma unroll
        for (int nt = 0; nt < 4; nt++)
            #pragma unroll
            for (int r = 0; r < 4; r++) acc[mt][nt][r] = 0.f;

    const size_t xbase = (size_t)b * C_DIM * T_DIM;

    for (int k0 = 0; k0 < C_DIM; k0 += BK) {
        // ---- load W tile: BK x BM = 3072 floats, 12 per thread ----
        #pragma unroll
        for (int j = 0; j < 12; j++) {
            int idx = tid + 256 * j;
            int k = idx / BM;
            int m = idx - k * BM;
            int ct = k0 + k;
            int mm = mtile + m;
            float v = 0.f;
            if (ct < C_DIM && mm < O_DIM) v = g_wT[ct * O_DIM + mm];
            sA[k][m] = __uint_as_float(f2tf(v));
        }
        // ---- load x tile: BK x BN, float4, 4 per thread ----
        #pragma unroll
        for (int j = 0; j < 4; j++) {
            int k = bk + 8 * j;
            int ct = k0 + k;
            int t = ntile + bn;
            float4 v = make_float4(0.f, 0.f, 0.f, 0.f);
            if (ct < C_DIM && t + 3 < T_DIM)
                v = *(const float4*)&x[xbase + (size_t)ct * T_DIM + t];
            v.x = __uint_as_float(f2tf(v.x));
            v.y = __uint_as_float(f2tf(v.y));
            v.z = __uint_as_float(f2tf(v.z));
            v.w = __uint_as_float(f2tf(v.w));
            *(float4*)&sB[k][bn] = v;
        }
        __syncthreads();

        // ---- 4 x k8 mma steps ----
        #pragma unroll
        for (int kk = 0; kk < BK; kk += 8) {
            unsigned a[3][4], bb[4][2];
            #pragma unroll
            for (int mt = 0; mt < 3; mt++) {
                int mb = wm * 48 + mt * 16 + g;
                a[mt][0] = __float_as_uint(sA[kk + tig][mb]);
                a[mt][1] = __float_as_uint(sA[kk + tig][mb + 8]);
                a[mt][2] = __float_as_uint(sA[kk + tig + 4][mb]);
                a[mt][3] = __float_as_uint(sA[kk + tig + 4][mb + 8]);
            }
            #pragma unroll
            for (int nt = 0; nt < 4; nt++) {
                int nb = wn * 32 + nt * 8 + g;
                bb[nt][0] = __float_as_uint(sB[kk + tig][nb]);
                bb[nt][1] = __float_as_uint(sB[kk + tig + 4][nb]);
            }
            #pragma unroll
            for (int mt = 0; mt < 3; mt++)
                #pragma unroll
                for (int nt = 0; nt < 4; nt++)
                    mma_tf32(acc[mt][nt], a[mt], bb[nt]);
        }
        __syncthreads();
    }

    // ---- store: float2 pairs (t0 even, T_DIM even -> never straddles) ----
    const size_t obase = (size_t)b * O_DIM * T_DIM;
    #pragma unroll
    for (int mt = 0; mt < 3; mt++) {
        #pragma unroll
        for (int nt = 0; nt < 4; nt++) {
            int m0 = mtile + wm * 48 + mt * 16 + g;
            int t0 = ntile + wn * 32 + nt * 8 + 2 * tig;
            if (t0 < T_DIM) {
                if (m0 < O_DIM) {
                    float2 v = make_float2(acc[mt][nt][0], acc[mt][nt][1]);
                    *(float2*)&out[obase + (size_t)m0 * T_DIM + t0] = v;
                }
                if (m0 + 8 < O_DIM) {
                    float2 v = make_float2(acc[mt][nt][2], acc[mt][nt][3]);
                    *(float2*)&out[obase + (size_t)(m0 + 8) * T_DIM + t0] = v;
                }
            }
        }
    }
}

extern "C" void kernel_launch(void* const* d_in, const int* in_sizes, int n_in,
                              void* d_out, int out_size) {
    const float* x      = (const float*)d_in[0];  // [B, C, T]
    const float* layout = (const float*)d_in[1];  // [C, 2]
    const float* heads  = (const float*)d_in[2];  // [O, D]
    float* out          = (float*)d_out;          // [B, O, T]

    int B = in_sizes[0] / (C_DIM * T_DIM);

    emb_kernel<<<C_DIM, 256>>>(layout);
    scores_kernel<<<dim3((C_DIM + 31) / 32, (O_DIM + 31) / 32), 256>>>(heads);
    softmax_kernel<<<O_DIM, 256>>>();
    merge_gemm<<<dim3((T_DIM + BN - 1) / BN, (O_DIM + BM - 1) / BM, B), 256>>>(x, out);
}

// round 7
// speedup vs baseline: 1.8716x; 1.8716x over previous
#include <cuda_runtime.h>
#include <cstdint>
#include <math.h>

#define C_DIM 270
#define T_DIM 2000
#define O_DIM 270
#define D_DIM 2048
#define NF2   1024

#define BM 96
#define BN 128
#define BK 16
#define NIT 18            // 18*16 = 288 >= 270
#define STAGES 3
#define SA_STRIDE 104     // stride % 32 == 8 -> conflict-free frag loads
#define SB_STRIDE 136

#define WP 288            // padded W dim (zero-filled -> no predicates in A loader)
#define SK 8              // split-K factor for scores
#define KCH (D_DIM / SK)  // 256

// Scratch (device globals are zero-initialized at module load; padding rows of
// g_wTp are never written -> stay zero forever)
__device__ float g_emb[C_DIM * D_DIM];          // [c][d]
__device__ float g_part[SK][O_DIM][272];        // split-K partial scores
__device__ float g_wTp[WP * WP];                // W^T, tf32-rounded, zero-padded

__device__ __forceinline__ unsigned f2tf(float x) {
    unsigned u;
    asm("cvt.rna.tf32.f32 %0, %1;" : "=r"(u) : "f"(x));
    return u;
}

__device__ __forceinline__ void mma_tf32(float* d, const unsigned* a, const unsigned* b) {
    asm volatile(
        "mma.sync.aligned.m16n8k8.row.col.f32.tf32.tf32.f32 "
        "{%0,%1,%2,%3}, {%4,%5,%6,%7}, {%8,%9}, {%0,%1,%2,%3};\n"
        : "+f"(d[0]), "+f"(d[1]), "+f"(d[2]), "+f"(d[3])
        : "r"(a[0]), "r"(a[1]), "r"(a[2]), "r"(a[3]), "r"(b[0]), "r"(b[1]));
}

// ---------------- Kernel 1: Fourier embedding (batch-invariant) ----------------
__global__ void emb_kernel(const float* __restrict__ layout) {
    int c = blockIdx.x;
    float px = layout[2 * c]     + 0.2f;
    float py = layout[2 * c + 1] + 0.2f;
    const float w = 6.28318530717958647692f / 1.4f;
    for (int idx = threadIdx.x; idx < NF2; idx += blockDim.x) {
        int i = idx >> 5, j = idx & 31;
        float loc = px * (w * (float)i) + py * (w * (float)j);
        float s, co;
        sincosf(loc, &s, &co);
        g_emb[c * D_DIM + idx]       = co;
        g_emb[c * D_DIM + NF2 + idx] = s;
    }
}

// -------- Kernel 2: split-K fp32 scores. part[s][o][c] = sum_{d in chunk s} ----
__global__ void __launch_bounds__(256) scores_splitk(const float* __restrict__ heads) {
    __shared__ float sH[16][68];   // [d][o]
    __shared__ float sE[16][68];   // [d][c]
    int tid = threadIdx.x;
    int ctile = blockIdx.x * 64;
    int otile = blockIdx.y * 64;
    int split = blockIdx.z;
    int tx = tid & 15, ty = tid >> 4;
    int lrow = tid >> 2;      // 0..63
    int ldq  = tid & 3;       // 0..3

    float acc[4][4];
    #pragma unroll
    for (int i = 0; i < 4; i++)
        #pragma unroll
        for (int j = 0; j < 4; j++) acc[i][j] = 0.f;

    for (int kt = 0; kt < KCH; kt += 16) {
        int d0 = split * KCH + kt;
        {
            int o = otile + lrow;
            float4 v = make_float4(0.f, 0.f, 0.f, 0.f);
            if (o < O_DIM) v = *(const float4*)&heads[(size_t)o * D_DIM + d0 + 4 * ldq];
            sH[4 * ldq + 0][lrow] = v.x; sH[4 * ldq + 1][lrow] = v.y;
            sH[4 * ldq + 2][lrow] = v.z; sH[4 * ldq + 3][lrow] = v.w;
        }
        {
            int c = ctile + lrow;
            float4 v = make_float4(0.f, 0.f, 0.f, 0.f);
            if (c < C_DIM) v = *(const float4*)&g_emb[(size_t)c * D_DIM + d0 + 4 * ldq];
            sE[4 * ldq + 0][lrow] = v.x; sE[4 * ldq + 1][lrow] = v.y;
            sE[4 * ldq + 2][lrow] = v.z; sE[4 * ldq + 3][lrow] = v.w;
        }
        __syncthreads();
        #pragma unroll
        for (int k = 0; k < 16; k++) {
            float4 h = *(float4*)&sH[k][ty * 4];
            float4 e = *(float4*)&sE[k][tx * 4];
            float hv[4] = {h.x, h.y, h.z, h.w};
            float ev[4] = {e.x, e.y, e.z, e.w};
            #pragma unroll
            for (int i = 0; i < 4; i++)
                #pragma unroll
                for (int j = 0; j < 4; j++) acc[i][j] += hv[i] * ev[j];
        }
        __syncthreads();
    }

    #pragma unroll
    for (int i = 0; i < 4; i++) {
        int o = otile + ty * 4 + i;
        if (o < O_DIM) {
            #pragma unroll
            for (int j = 0; j < 4; j++) {
                int c = ctile + tx * 4 + j;
                if (c < C_DIM) g_part[split][o][c] = acc[i][j];
            }
        }
    }
}

// ------ Kernel 3: reduce partials + softmax over c, store tf32 W^T padded -----
__global__ void softmax_kernel() {
    int o = blockIdx.x;
    int tid = threadIdx.x;
    __shared__ float sc[C_DIM];
    __shared__ float red[256];

    for (int c = tid; c < C_DIM; c += 256) {
        float s = 0.f;
        #pragma unroll
        for (int p = 0; p < SK; p++) s += g_part[p][o][c];
        sc[c] = s;
    }
    __syncthreads();

    float m = -1e30f;
    for (int c = tid; c < C_DIM; c += 256) m = fmaxf(m, sc[c]);
    red[tid] = m; __syncthreads();
    for (int s = 128; s > 0; s >>= 1) {
        if (tid < s) red[tid] = fmaxf(red[tid], red[tid + s]);
        __syncthreads();
    }
    m = red[0]; __syncthreads();

    float sum = 0.f;
    for (int c = tid; c < C_DIM; c += 256) {
        float e = expf(sc[c] - m);
        sc[c] = e;
        sum += e;
    }
    red[tid] = sum; __syncthreads();
    for (int s = 128; s > 0; s >>= 1) {
        if (tid < s) red[tid] += red[tid + s];
        __syncthreads();
    }
    float inv = 1.0f / red[0];
    __syncthreads();

    for (int c = tid; c < C_DIM; c += 256)
        g_wTp[c * WP + o] = __uint_as_float(f2tf(sc[c] * inv));
}

// ---------------- Kernel 4: out[b] = W @ x[b], cp.async 3-stage pipeline ------
__global__ void __launch_bounds__(256, 2) merge_gemm(const float* __restrict__ x,
                                                      float* __restrict__ out) {
    __shared__ float sA[STAGES][BK][SA_STRIDE];  // 19.5 KB
    __shared__ float sB[STAGES][BK][SB_STRIDE];  // 25.5 KB  (total 45 KB)

    int tid = threadIdx.x;
    int b = blockIdx.z;
    int mtile = blockIdx.y * BM;
    int ntile = blockIdx.x * BN;
    int lane = tid & 31, warp = tid >> 5;
    int wm = warp & 1;
    int wn = warp >> 1;
    int g = lane >> 2, tig = lane & 3;

    const float* xb = x + (size_t)b * C_DIM * T_DIM;

    float acc[3][4][4];
    #pragma unroll
    for (int mt = 0; mt < 3; mt++)
        #pragma unroll
        for (int nt = 0; nt < 4; nt++)
            #pragma unroll
            for (int r = 0; r < 4; r++) acc[mt][nt][r] = 0.f;

    // ---- loaders ----
    auto load_tile = [&](int s, int k0) {
        // A: 16x96 floats = 384 float4 (no predicates: g_wTp is 288x288 zero-padded)
        #pragma unroll
        for (int j = 0; j < 2; ++j) {
            int ff = tid + 256 * j;
            if (ff < 384) {
                int k = ff / 24;
                int m = (ff - k * 24) * 4;
                const float* src = &g_wTp[(k0 + k) * WP + mtile + m];
                uint32_t dst = (uint32_t)__cvta_generic_to_shared(&sA[s][k][m]);
                asm volatile("cp.async.cg.shared.global [%0], [%1], 16, 16;\n"
                             :: "r"(dst), "l"(src));
            }
        }
        // B: 16x128 floats = 512 float4
        #pragma unroll
        for (int j = 0; j < 2; ++j) {
            int ff = tid + 256 * j;
            int k = ff >> 5;
            int n = (ff & 31) * 4;
            int c = k0 + k;
            int t = ntile + n;
            bool pred = (c < C_DIM) && (t < T_DIM);
            const float* src = pred ? (xb + (size_t)c * T_DIM + t) : xb;
            int sz = pred ? 16 : 0;
            uint32_t dst = (uint32_t)__cvta_generic_to_shared(&sB[s][k][n]);
            asm volatile("cp.async.cg.shared.global [%0], [%1], 16, %2;\n"
                         :: "r"(dst), "l"(src), "r"(sz));
        }
    };

    // prologue: stages 0 and 1
    load_tile(0, 0);
    asm volatile("cp.async.commit_group;\n" ::: "memory");
    load_tile(1, BK);
    asm volatile("cp.async.commit_group;\n" ::: "memory");

    const int mb_base = wm * 48 + g;
    const int nb_base = wn * 32 + g;

    for (int it = 0; it < NIT; ++it) {
        asm volatile("cp.async.wait_group 1;\n" ::: "memory");
        __syncthreads();

        int pre = it + 2;
        if (pre < NIT) load_tile(pre % STAGES, pre * BK);
        asm volatile("cp.async.commit_group;\n" ::: "memory");

        const int st = it % STAGES;
        #pragma unroll
        for (int kk = 0; kk < BK; kk += 8) {
            unsigned a[3][4], bb[4][2];
            #pragma unroll
            for (int mt = 0; mt < 3; mt++) {
                int mb = mb_base + mt * 16;
                a[mt][0] = __float_as_uint(sA[st][kk + tig][mb]);
                a[mt][1] = __float_as_uint(sA[st][kk + tig][mb + 8]);
                a[mt][2] = __float_as_uint(sA[st][kk + tig + 4][mb]);
                a[mt][3] = __float_as_uint(sA[st][kk + tig + 4][mb + 8]);
            }
            #pragma unroll
            for (int nt = 0; nt < 4; nt++) {
                int nb = nb_base + nt * 8;
                bb[nt][0] = f2tf(sB[st][kk + tig][nb]);
                bb[nt][1] = f2tf(sB[st][kk + tig + 4][nb]);
            }
            #pragma unroll
            for (int mt = 0; mt < 3; mt++)
                #pragma unroll
                for (int nt = 0; nt < 4; nt++)
                    mma_tf32(acc[mt][nt], a[mt], bb[nt]);
        }
    }

    // ---- store ----
    const size_t obase = (size_t)b * O_DIM * T_DIM;
    #pragma unroll
    for (int mt = 0; mt < 3; mt++) {
        #pragma unroll
        for (int nt = 0; nt < 4; nt++) {
            int m0 = mtile + wm * 48 + mt * 16 + g;
            int t0 = ntile + wn * 32 + nt * 8 + 2 * tig;
            if (t0 < T_DIM) {
                if (m0 < O_DIM) {
                    float2 v = make_float2(acc[mt][nt][0], acc[mt][nt][1]);
                    *(float2*)&out[obase + (size_t)m0 * T_DIM + t0] = v;
                }
                if (m0 + 8 < O_DIM) {
                    float2 v = make_float2(acc[mt][nt][2], acc[mt][nt][3]);
                    *(float2*)&out[obase + (size_t)(m0 + 8) * T_DIM + t0] = v;
                }
            }
        }
    }
}

extern "C" void kernel_launch(void* const* d_in, const int* in_sizes, int n_in,
                              void* d_out, int out_size) {
    const float* x      = (const float*)d_in[0];  // [B, C, T]
    const float* layout = (const float*)d_in[1];  // [C, 2]
    const float* heads  = (const float*)d_in[2];  // [O, D]
    float* out          = (float*)d_out;          // [B, O, T]

    int B = in_sizes[0] / (C_DIM * T_DIM);

    emb_kernel<<<C_DIM, 256>>>(layout);
    scores_splitk<<<dim3(5, 5, SK), 256>>>(heads);
    softmax_kernel<<<O_DIM, 256>>>();
    merge_gemm<<<dim3((T_DIM + BN - 1) / BN, (O_DIM + BM - 1) / BM, B), 256>>>(x, out);
}